// round 2
// baseline (speedup 1.0000x reference)
#include <cuda_runtime.h>

// LSTMAggregator: index = repeat(arange(16384),16) -> dense batch LSTM
// B=16384, T=16, H=128. out = h_final (16384,128) fp32.

#define NN    16384
#define DEG   16
#define HD    128
#define G4    512
#define NT    64        // nodes per block
#define NTH   512       // threads per block (16 warps, warp owns 4 nodes)
#define KB    8         // k-slab depth
#define NSLAB 32        // 256 k / KB
#define KTOT  256
#define AS    66        // a-tile row stride in floats (even, !=0 mod 32 -> conflict-free)

typedef unsigned long long u64;

// ---- packed fp32x2 (Blackwell; ptxas never emits FFMA2 from C++) ----
__device__ __forceinline__ u64 pk2(float x, float y) {
    u64 r; asm("mov.b64 %0,{%1,%2};" : "=l"(r) : "f"(x), "f"(y)); return r;
}
__device__ __forceinline__ void upk2(u64 v, float &x, float &y) {
    asm("mov.b64 {%0,%1},%2;" : "=f"(x), "=f"(y) : "l"(v));
}
__device__ __forceinline__ u64 ffma2(u64 a, u64 b, u64 c) {
    u64 d; asm("fma.rn.f32x2 %0,%1,%2,%3;" : "=l"(d) : "l"(a), "l"(b), "l"(c)); return d;
}

// ---- activations (rel err ~1e-6, safe ranges) ----
__device__ __forceinline__ float sigf(float v) {
    float vc = fminf(fmaxf(v, -80.f), 80.f);
    float e = __expf(-vc);
    return __fdividef(1.f, 1.f + e);
}
__device__ __forceinline__ float tanhf_(float v) {
    float a = fabsf(v);
    float e = __expf(-2.f * a);            // in (0,1], never overflows
    float t = __fdividef(1.f - e, 1.f + e);
    return copysignf(t, v);
}

__global__ void __launch_bounds__(NTH, 1)
lstm_agg_kernel(const float* __restrict__ x,
                const float* __restrict__ Wih,
                const float* __restrict__ Whh,
                const float* __restrict__ bih,
                const float* __restrict__ bhh,
                float* __restrict__ out)
{
    extern __shared__ float sm[];
    float* atile = sm;                       // [256][AS]: rows 0..127 = x_t, 128..255 = h
    float* wsm   = sm + KTOT * AS;           // [2][KB][G4] W slab, double buffered
    float* bsm   = wsm + 2 * KB * G4;        // [512] bias

    const int tid   = threadIdx.x;
    const int tx    = tid & 31;
    const int ty    = tid >> 5;              // warp 0..15
    const int nodeW = ty * 4;                // warp's first local node
    const int node0 = blockIdx.x * NT;       // block's first global node
    const int jb0   = 2 * tx;                // col pair base; jp adds +64

    // bias to smem (NTH == G4)
    bsm[tid] = bih[tid] + bhh[tid];

    // zero h rows (warp-private) and c state
    float c[4][4];                           // [node m][jp*2+e]
#pragma unroll
    for (int m = 0; m < 4; m++)
#pragma unroll
        for (int jp = 0; jp < 2; jp++)
#pragma unroll
            for (int e = 0; e < 2; e++) {
                atile[(HD + jb0 + 64 * jp + e) * AS + nodeW + m] = 0.f;
                c[m][jp * 2 + e] = 0.f;
            }

    // x staging role: thread -> (node sn, k chunk skc of 16)
    const int sn  = tid & 63;
    const int skc = tid >> 6;                // 0..7

    u64 acc[4][4][2];                        // [node m][gate g][jp], lo/hi = cols (jb,jb+1)

#pragma unroll 1
    for (int t = 0; t < DEG; t++) {
        __syncthreads();   // prev step fully done (a-tile reads, wsm compute); bias/h-init visible

        // ---- stage x_t transposed: atile[k][node] ----
        const float* xrow = x + ((node0 + sn) * DEG + t) * HD + skc * 16;
        float4 xv[4];
#pragma unroll
        for (int i = 0; i < 4; i++) xv[i] = ((const float4*)xrow)[i];

        // prologue: W slab 0 into regs (k0 = 0 -> Wih)
        float4 w0 = *(const float4*)(Wih + tid * HD);
        float4 w1 = *(const float4*)(Wih + tid * HD + 4);

#pragma unroll
        for (int i = 0; i < 4; i++) {
            int k = skc * 16 + 4 * i;
            atile[(k + 0) * AS + sn] = xv[i].x;
            atile[(k + 1) * AS + sn] = xv[i].y;
            atile[(k + 2) * AS + sn] = xv[i].z;
            atile[(k + 3) * AS + sn] = xv[i].w;
        }

        // init accumulators from bias (packed pairs straight from smem)
#pragma unroll
        for (int g = 0; g < 4; g++)
#pragma unroll
            for (int jp = 0; jp < 2; jp++) {
                u64 bv = *(const u64*)(bsm + g * HD + jb0 + 64 * jp);
                acc[0][g][jp] = bv; acc[1][g][jp] = bv;
                acc[2][g][jp] = bv; acc[3][g][jp] = bv;
            }

        __syncthreads();   // x tile visible to all warps

        // ---- GEMM: gates[64][512] += a[64][256] @ W[256][512], W streamed ----
        int buf = 0;
#pragma unroll 1
        for (int s = 0; s < NSLAB; s++) {
            // store current slab (regs -> smem), transposed: wsm[kk][row]
            float* wb = wsm + buf * (KB * G4);
            wb[0 * G4 + tid] = w0.x; wb[1 * G4 + tid] = w0.y;
            wb[2 * G4 + tid] = w0.z; wb[3 * G4 + tid] = w0.w;
            wb[4 * G4 + tid] = w1.x; wb[5 * G4 + tid] = w1.y;
            wb[6 * G4 + tid] = w1.z; wb[7 * G4 + tid] = w1.w;

            // prefetch next slab into regs (hidden under this slab's compute)
            if (s + 1 < NSLAB) {
                int k0 = (s + 1) * KB;
                const float* src = (k0 < HD) ? (Wih + tid * HD + k0)
                                             : (Whh + tid * HD + (k0 - HD));
                w0 = *(const float4*)(src);
                w1 = *(const float4*)(src + 4);
            }
            __syncthreads();

            const float* wk = wsm + buf * (KB * G4);
#pragma unroll
            for (int kk = 0; kk < KB; kk++) {
                int k = s * KB + kk;
                const float* arow = atile + k * AS + nodeW;   // broadcast loads
                u64 av0 = pk2(arow[0], arow[0]);
                u64 av1 = pk2(arow[1], arow[1]);
                u64 av2 = pk2(arow[2], arow[2]);
                u64 av3 = pk2(arow[3], arow[3]);
                const float* wrow = wk + kk * G4;
#pragma unroll
                for (int g = 0; g < 4; g++)
#pragma unroll
                    for (int jp = 0; jp < 2; jp++) {
                        u64 wv = *(const u64*)(wrow + g * HD + jb0 + 64 * jp);
                        acc[0][g][jp] = ffma2(av0, wv, acc[0][g][jp]);
                        acc[1][g][jp] = ffma2(av1, wv, acc[1][g][jp]);
                        acc[2][g][jp] = ffma2(av2, wv, acc[2][g][jp]);
                        acc[3][g][jp] = ffma2(av3, wv, acc[3][g][jp]);
                    }
            }
            buf ^= 1;
        }

        // ---- elementwise LSTM cell + h/out write ----
#pragma unroll
        for (int m = 0; m < 4; m++) {
#pragma unroll
            for (int jp = 0; jp < 2; jp++) {
                float i0, i1, f0, f1, g0, g1, o0, o1;
                upk2(acc[m][0][jp], i0, i1);
                upk2(acc[m][1][jp], f0, f1);
                upk2(acc[m][2][jp], g0, g1);
                upk2(acc[m][3][jp], o0, o1);
                i0 = sigf(i0);   i1 = sigf(i1);
                f0 = sigf(f0);   f1 = sigf(f1);
                g0 = tanhf_(g0); g1 = tanhf_(g1);
                o0 = sigf(o0);   o1 = sigf(o1);
                float c0 = f0 * c[m][jp * 2 + 0] + i0 * g0;
                float c1 = f1 * c[m][jp * 2 + 1] + i1 * g1;
                c[m][jp * 2 + 0] = c0;
                c[m][jp * 2 + 1] = c1;
                float h0 = o0 * tanhf_(c0);
                float h1 = o1 * tanhf_(c1);
                if (t == DEG - 1) {
                    // coalesced float2 store of final h
                    *(float2*)(out + (node0 + nodeW + m) * HD + jb0 + 64 * jp)
                        = make_float2(h0, h1);
                } else {
                    atile[(HD + jb0 + 64 * jp + 0) * AS + nodeW + m] = h0;
                    atile[(HD + jb0 + 64 * jp + 1) * AS + nodeW + m] = h1;
                }
            }
        }
    }
}

extern "C" void kernel_launch(void* const* d_in, const int* in_sizes, int n_in,
                              void* d_out, int out_size)
{
    // classify inputs by size (robust to dim_size scalar placement):
    // x = 16384*16*128 = 33554432, W = 512*128 = 65536 (ih first, hh second),
    // b = 512 (ih first, hh second); index (262144) and dim_size (1) unused.
    const float *x = nullptr, *Wih = nullptr, *Whh = nullptr;
    const float *bih = nullptr, *bhh = nullptr;
    for (int i = 0; i < n_in; i++) {
        int sz = in_sizes[i];
        if (sz == NN * DEG * HD)      { x = (const float*)d_in[i]; }
        else if (sz == G4 * HD)       { if (!Wih) Wih = (const float*)d_in[i];
                                        else if (!Whh) Whh = (const float*)d_in[i]; }
        else if (sz == G4)            { if (!bih) bih = (const float*)d_in[i];
                                        else if (!bhh) bhh = (const float*)d_in[i]; }
    }
    float* out = (float*)d_out;

    int smem = (KTOT * AS + 2 * KB * G4 + G4) * (int)sizeof(float);   // 102400 B
    cudaFuncSetAttribute(lstm_agg_kernel,
                         cudaFuncAttributeMaxDynamicSharedMemorySize, smem);
    lstm_agg_kernel<<<NN / NT, NTH, smem>>>(x, Wih, Whh, bih, bhh, out);
}

// round 3
// speedup vs baseline: 1.0018x; 1.0018x over previous
#include <cuda_runtime.h>

// LSTMAggregator: index = repeat(arange(16384),16) -> dense batch LSTM
// B=16384, T=16, H=128. out = h_final (16384,128) fp32.

#define NN    16384
#define DEG   16
#define HD    128
#define G4    512
#define NT    64        // nodes per block
#define NTH   512       // threads per block (16 warps, warp owns 4 nodes)
#define KB    8         // k-slab depth
#define NSLAB 32        // 256 k / KB
#define KTOT  256
#define AS    66        // a-tile row stride in floats (even, !=0 mod 32 -> conflict-free)

typedef unsigned long long u64;

// ---- packed fp32x2 (Blackwell; ptxas never emits FFMA2 from C++) ----
__device__ __forceinline__ u64 pk2(float x, float y) {
    u64 r; asm("mov.b64 %0,{%1,%2};" : "=l"(r) : "f"(x), "f"(y)); return r;
}
__device__ __forceinline__ void upk2(u64 v, float &x, float &y) {
    asm("mov.b64 {%0,%1},%2;" : "=f"(x), "=f"(y) : "l"(v));
}
__device__ __forceinline__ u64 ffma2(u64 a, u64 b, u64 c) {
    u64 d; asm("fma.rn.f32x2 %0,%1,%2,%3;" : "=l"(d) : "l"(a), "l"(b), "l"(c)); return d;
}

// ---- activations (rel err ~1e-6, safe ranges) ----
__device__ __forceinline__ float sigf(float v) {
    float vc = fminf(fmaxf(v, -80.f), 80.f);
    float e = __expf(-vc);
    return __fdividef(1.f, 1.f + e);
}
__device__ __forceinline__ float tanhf_(float v) {
    float a = fabsf(v);
    float e = __expf(-2.f * a);            // in (0,1], never overflows
    float t = __fdividef(1.f - e, 1.f + e);
    return copysignf(t, v);
}

__global__ void __launch_bounds__(NTH, 1)
lstm_agg_kernel(const float* __restrict__ x,
                const float* __restrict__ Wih,
                const float* __restrict__ Whh,
                const float* __restrict__ bih,
                const float* __restrict__ bhh,
                float* __restrict__ out)
{
    extern __shared__ float sm[];
    float* atile = sm;                       // [256][AS]: rows 0..127 = x_t, 128..255 = h
    float* wsm   = sm + KTOT * AS;           // [2][KB][G4] W slab, double buffered
    float* bsm   = wsm + 2 * KB * G4;        // [512] bias

    const int tid   = threadIdx.x;
    const int tx    = tid & 31;
    const int ty    = tid >> 5;              // warp 0..15
    const int nodeW = ty * 4;                // warp's first local node
    const int node0 = blockIdx.x * NT;       // block's first global node
    const int jb0   = 2 * tx;                // col pair base; jp adds +64

    // bias to smem (NTH == G4)
    bsm[tid] = bih[tid] + bhh[tid];

    // zero h rows (warp-private) and c state
    float c[4][4];                           // [node m][jp*2+e]
#pragma unroll
    for (int m = 0; m < 4; m++)
#pragma unroll
        for (int jp = 0; jp < 2; jp++)
#pragma unroll
            for (int e = 0; e < 2; e++) {
                atile[(HD + jb0 + 64 * jp + e) * AS + nodeW + m] = 0.f;
                c[m][jp * 2 + e] = 0.f;
            }

    // x staging role: thread -> (node sn, k chunk skc of 16)
    const int sn  = tid & 63;
    const int skc = tid >> 6;                // 0..7

    u64 acc[4][4][2];                        // [node m][gate g][jp], lo/hi = cols (jb,jb+1)

#pragma unroll 1
    for (int t = 0; t < DEG; t++) {
        __syncthreads();   // prev step fully done (a-tile reads, wsm compute); bias/h-init visible

        // ---- stage x_t transposed: atile[k][node] ----
        const float* xrow = x + ((node0 + sn) * DEG + t) * HD + skc * 16;
        float4 xv[4];
#pragma unroll
        for (int i = 0; i < 4; i++) xv[i] = ((const float4*)xrow)[i];

        // prologue: W slab 0 into regs (k0 = 0 -> Wih)
        float4 w0 = *(const float4*)(Wih + tid * HD);
        float4 w1 = *(const float4*)(Wih + tid * HD + 4);

#pragma unroll
        for (int i = 0; i < 4; i++) {
            int k = skc * 16 + 4 * i;
            atile[(k + 0) * AS + sn] = xv[i].x;
            atile[(k + 1) * AS + sn] = xv[i].y;
            atile[(k + 2) * AS + sn] = xv[i].z;
            atile[(k + 3) * AS + sn] = xv[i].w;
        }

        // init accumulators from bias (packed pairs straight from smem)
#pragma unroll
        for (int g = 0; g < 4; g++)
#pragma unroll
            for (int jp = 0; jp < 2; jp++) {
                u64 bv = *(const u64*)(bsm + g * HD + jb0 + 64 * jp);
                acc[0][g][jp] = bv; acc[1][g][jp] = bv;
                acc[2][g][jp] = bv; acc[3][g][jp] = bv;
            }

        __syncthreads();   // x tile visible to all warps

        // ---- GEMM: gates[64][512] += a[64][256] @ W[256][512], W streamed ----
        int buf = 0;
#pragma unroll 1
        for (int s = 0; s < NSLAB; s++) {
            // store current slab (regs -> smem), transposed: wsm[kk][row]
            float* wb = wsm + buf * (KB * G4);
            wb[0 * G4 + tid] = w0.x; wb[1 * G4 + tid] = w0.y;
            wb[2 * G4 + tid] = w0.z; wb[3 * G4 + tid] = w0.w;
            wb[4 * G4 + tid] = w1.x; wb[5 * G4 + tid] = w1.y;
            wb[6 * G4 + tid] = w1.z; wb[7 * G4 + tid] = w1.w;

            // prefetch next slab into regs (hidden under this slab's compute)
            if (s + 1 < NSLAB) {
                int k0 = (s + 1) * KB;
                const float* src = (k0 < HD) ? (Wih + tid * HD + k0)
                                             : (Whh + tid * HD + (k0 - HD));
                w0 = *(const float4*)(src);
                w1 = *(const float4*)(src + 4);
            }
            __syncthreads();

            const float* wk = wsm + buf * (KB * G4);
#pragma unroll
            for (int kk = 0; kk < KB; kk++) {
                int k = s * KB + kk;
                const float* arow = atile + k * AS + nodeW;   // broadcast loads
                u64 av0 = pk2(arow[0], arow[0]);
                u64 av1 = pk2(arow[1], arow[1]);
                u64 av2 = pk2(arow[2], arow[2]);
                u64 av3 = pk2(arow[3], arow[3]);
                const float* wrow = wk + kk * G4;
#pragma unroll
                for (int g = 0; g < 4; g++)
#pragma unroll
                    for (int jp = 0; jp < 2; jp++) {
                        u64 wv = *(const u64*)(wrow + g * HD + jb0 + 64 * jp);
                        acc[0][g][jp] = ffma2(av0, wv, acc[0][g][jp]);
                        acc[1][g][jp] = ffma2(av1, wv, acc[1][g][jp]);
                        acc[2][g][jp] = ffma2(av2, wv, acc[2][g][jp]);
                        acc[3][g][jp] = ffma2(av3, wv, acc[3][g][jp]);
                    }
            }
            buf ^= 1;
        }

        // ---- elementwise LSTM cell + h/out write ----
#pragma unroll
        for (int m = 0; m < 4; m++) {
#pragma unroll
            for (int jp = 0; jp < 2; jp++) {
                float i0, i1, f0, f1, g0, g1, o0, o1;
                upk2(acc[m][0][jp], i0, i1);
                upk2(acc[m][1][jp], f0, f1);
                upk2(acc[m][2][jp], g0, g1);
                upk2(acc[m][3][jp], o0, o1);
                i0 = sigf(i0);   i1 = sigf(i1);
                f0 = sigf(f0);   f1 = sigf(f1);
                g0 = tanhf_(g0); g1 = tanhf_(g1);
                o0 = sigf(o0);   o1 = sigf(o1);
                float c0 = f0 * c[m][jp * 2 + 0] + i0 * g0;
                float c1 = f1 * c[m][jp * 2 + 1] + i1 * g1;
                c[m][jp * 2 + 0] = c0;
                c[m][jp * 2 + 1] = c1;
                float h0 = o0 * tanhf_(c0);
                float h1 = o1 * tanhf_(c1);
                if (t == DEG - 1) {
                    // coalesced float2 store of final h
                    *(float2*)(out + (node0 + nodeW + m) * HD + jb0 + 64 * jp)
                        = make_float2(h0, h1);
                } else {
                    atile[(HD + jb0 + 64 * jp + 0) * AS + nodeW + m] = h0;
                    atile[(HD + jb0 + 64 * jp + 1) * AS + nodeW + m] = h1;
                }
            }
        }
    }
}

extern "C" void kernel_launch(void* const* d_in, const int* in_sizes, int n_in,
                              void* d_out, int out_size)
{
    // classify inputs by size (robust to dim_size scalar placement):
    // x = 16384*16*128 = 33554432, W = 512*128 = 65536 (ih first, hh second),
    // b = 512 (ih first, hh second); index (262144) and dim_size (1) unused.
    const float *x = nullptr, *Wih = nullptr, *Whh = nullptr;
    const float *bih = nullptr, *bhh = nullptr;
    for (int i = 0; i < n_in; i++) {
        int sz = in_sizes[i];
        if (sz == NN * DEG * HD)      { x = (const float*)d_in[i]; }
        else if (sz == G4 * HD)       { if (!Wih) Wih = (const float*)d_in[i];
                                        else if (!Whh) Whh = (const float*)d_in[i]; }
        else if (sz == G4)            { if (!bih) bih = (const float*)d_in[i];
                                        else if (!bhh) bhh = (const float*)d_in[i]; }
    }
    float* out = (float*)d_out;

    int smem = (KTOT * AS + 2 * KB * G4 + G4) * (int)sizeof(float);   // 102400 B
    cudaFuncSetAttribute(lstm_agg_kernel,
                         cudaFuncAttributeMaxDynamicSharedMemorySize, smem);
    lstm_agg_kernel<<<NN / NT, NTH, smem>>>(x, Wih, Whh, bih, bhh, out);
}